// round 9
// baseline (speedup 1.0000x reference)
#include <cuda_runtime.h>

// Per-quaternion L2 normalize: (65536, 1024) fp32 = 2^24 quats.
// 512 MiB mandatory HBM traffic (256 in + 256 out).
//
// Optimization history (GB300, sm_103a):
//   R1 MLP2  T256:        5955 GB/s   wall 82.7us
//   R2 MLP4  T256:        6479 GB/s   wall 82.0us   <- plateau
//   R3 MLP8  T256:        6324 GB/s   (regs 40 -> occ 62%) regression
//   R4 MLP4  T512:        6451 GB/s   wall 81.95us  <- best, reproduced R8
//   R5 persistent loop:   6077 GB/s   wall 92.2us   regression
//   R6 2x256-bit ld/st:   6491 GB/s   wall 82.3us   == plateau
//   R7 3x256-bit + tail:  plateau + launch overhead, wall 84.1us
//   R8 re-bench of R4:    wall 81.952us (reproducible)
//
// The ~6.49 TB/s plateau is the HBM3e r/w streaming ceiling. R9 probes the
// one untested knob: store cache policy. Loads stay .cs (evict-first, no
// reuse); stores switch .cs -> default .wb so L2 write-combines full 128B
// lines before draining to HBM (better write-burst scheduling vs the
// evict-first early-writeback behavior of .cs stores).

static __device__ __forceinline__ float4 norm_quat(float4 v) {
    float s = v.x * v.x + v.y * v.y + v.z * v.z + v.w * v.w;
    // reference semantics: ||x||==0 -> divide by 1 (pass through).
    float inv = (s == 0.0f) ? 1.0f : rsqrtf(s);
    v.x *= inv; v.y *= inv; v.z *= inv; v.w *= inv;
    return v;
}

__global__ void __launch_bounds__(512)
quat_normalize_kernel(const float4* __restrict__ in,
                      float4* __restrict__ out) {
    const int T = 512;
    int base = blockIdx.x * (T * 4) + threadIdx.x;

    // Front-batch 4 independent, warp-coalesced 16B loads (MLP_p1 = 4,
    // 64B in flight per thread — the measured optimum), evict-first.
    float4 a = __ldcs(&in[base]);
    float4 b = __ldcs(&in[base + T]);
    float4 c = __ldcs(&in[base + 2 * T]);
    float4 d = __ldcs(&in[base + 3 * T]);

    // Stores: default write-back (L2 accumulates full lines, drains in
    // large bursts). Each result retires as soon as it's ready.
    a = norm_quat(a);
    out[base] = a;
    b = norm_quat(b);
    out[base + T] = b;
    c = norm_quat(c);
    out[base + 2 * T] = c;
    d = norm_quat(d);
    out[base + 3 * T] = d;
}

// Bounds-checked fallback for non-multiple sizes (unused for 2^24 quats).
__global__ void __launch_bounds__(256)
quat_normalize_tail_kernel(const float4* __restrict__ in,
                           float4* __restrict__ out,
                           int n_quat) {
    int i = blockIdx.x * blockDim.x + threadIdx.x;
    if (i < n_quat) out[i] = norm_quat(__ldcs(&in[i]));
}

extern "C" void kernel_launch(void* const* d_in, const int* in_sizes, int n_in,
                              void* d_out, int out_size) {
    const float4* x = (const float4*)d_in[0];
    float4* y = (float4*)d_out;
    int n_quat = in_sizes[0] / 4;   // 16,777,216

    const int threads = 512;
    const int per_block = threads * 4;  // 2048 quats/block

    if (n_quat % per_block == 0) {
        quat_normalize_kernel<<<n_quat / per_block, threads>>>(x, y);  // 8192 blocks
    } else {
        int main_blocks = n_quat / per_block;
        if (main_blocks > 0)
            quat_normalize_kernel<<<main_blocks, threads>>>(x, y);
        int done = main_blocks * per_block;
        int rem = n_quat - done;
        if (rem > 0)
            quat_normalize_tail_kernel<<<(rem + 255) / 256, 256>>>(
                x + done, y + done, rem);
    }
}

// round 10
// speedup vs baseline: 1.0004x; 1.0004x over previous
#include <cuda_runtime.h>

// Per-quaternion L2 normalize: (65536, 1024) fp32 = 2^24 quats.
// 512 MiB mandatory HBM traffic (256 in + 256 out).
//
// FINAL KERNEL — session closed at the HBM roofline.
//
// Optimization history (GB300, sm_103a):
//   R1 MLP2  T256:        5955 GB/s   wall 82.7us
//   R2 MLP4  T256:        6479 GB/s   wall 82.0us
//   R3 MLP8  T256:        6324 GB/s   (regs 40 -> occ 62%) regression
//   R4 MLP4  T512 .cs:    6451 GB/s   wall 81.952us  <- BEST
//   R5 persistent loop:   6077 GB/s   wall 92.2us    regression
//   R6 2x256-bit ld/st:   6491 GB/s   wall 82.3us    == plateau
//   R7 3x256-bit + tail:  plateau + extra launch, wall 84.1us
//   R8 re-bench R4:       wall 81.952us (reproducible)
//   R9 .wb stores:        wall 82.016us (store policy irrelevant)
//
// Conclusion: every in-SM lever swept (MLP 32/64/96/128 B per thread, block
// size, persistence, 128/256-bit encodings, load/store cache ops). All top
// configs saturate at ~6.45-6.49 TB/s; 512 MiB at that rate == the pinned
// ~82us wall. The LTS/HBM streaming cap is path-independent (LDG == TMA per
// B300 microarch), and the byte traffic is irreducible, so this is the
// roofline. Final = best measured config (R4).

static __device__ __forceinline__ float4 norm_quat(float4 v) {
    float s = v.x * v.x + v.y * v.y + v.z * v.z + v.w * v.w;
    // reference semantics: ||x||==0 -> divide by 1 (pass through).
    float inv = (s == 0.0f) ? 1.0f : rsqrtf(s);
    v.x *= inv; v.y *= inv; v.z *= inv; v.w *= inv;
    return v;
}

__global__ void __launch_bounds__(512)
quat_normalize_kernel(const float4* __restrict__ in,
                      float4* __restrict__ out) {
    const int T = 512;
    int base = blockIdx.x * (T * 4) + threadIdx.x;

    // Front-batch 4 independent, warp-coalesced 16B loads (MLP_p1 = 4,
    // 64B in flight per thread — the measured optimum), evict-first.
    float4 a = __ldcs(&in[base]);
    float4 b = __ldcs(&in[base + T]);
    float4 c = __ldcs(&in[base + 2 * T]);
    float4 d = __ldcs(&in[base + 3 * T]);

    // Store each result as soon as it's ready: short live ranges (30 regs),
    // early start of the write stream.
    a = norm_quat(a);
    __stcs(&out[base], a);
    b = norm_quat(b);
    __stcs(&out[base + T], b);
    c = norm_quat(c);
    __stcs(&out[base + 2 * T], c);
    d = norm_quat(d);
    __stcs(&out[base + 3 * T], d);
}

// Bounds-checked fallback for non-multiple sizes (unused for 2^24 quats).
__global__ void __launch_bounds__(256)
quat_normalize_tail_kernel(const float4* __restrict__ in,
                           float4* __restrict__ out,
                           int n_quat) {
    int i = blockIdx.x * blockDim.x + threadIdx.x;
    if (i < n_quat) out[i] = norm_quat(__ldcs(&in[i]));
}

extern "C" void kernel_launch(void* const* d_in, const int* in_sizes, int n_in,
                              void* d_out, int out_size) {
    const float4* x = (const float4*)d_in[0];
    float4* y = (float4*)d_out;
    int n_quat = in_sizes[0] / 4;   // 16,777,216

    const int threads = 512;
    const int per_block = threads * 4;  // 2048 quats/block

    if (n_quat % per_block == 0) {
        quat_normalize_kernel<<<n_quat / per_block, threads>>>(x, y);  // 8192 blocks
    } else {
        int main_blocks = n_quat / per_block;
        if (main_blocks > 0)
            quat_normalize_kernel<<<main_blocks, threads>>>(x, y);
        int done = main_blocks * per_block;
        int rem = n_quat - done;
        if (rem > 0)
            quat_normalize_tail_kernel<<<(rem + 255) / 256, 256>>>(
                x + done, y + done, rem);
    }
}